// round 1
// baseline (speedup 1.0000x reference)
#include <cuda_runtime.h>
#include <cuda_bf16.h>
#include <math.h>

// Problem constants (fixed by the dataset: B=4, H=W=320)
#define H_DIM 320
#define W_DIM 320
#define B_DIM 4
#define TILE 32
#define HALO 8
#define STILE (TILE + 2 * HALO)          // 48
#define NBLK_X (W_DIM / TILE)            // 10
#define NBLK_Y (H_DIM / TILE)            // 10
#define NBLOCKS (NBLK_X * NBLK_Y * B_DIM) // 400

__device__ double g_blockSums[NBLOCKS];

// ---------------------------------------------------------------------------
// Kernel 1: fused exact-EDT (expanding ring search) + sigmoid + loss reduce
// ---------------------------------------------------------------------------
__global__ __launch_bounds__(1024, 1)
void edt_loss_kernel(const float* __restrict__ logits,
                     const int* __restrict__ targets)
{
    __shared__ unsigned char s_seed[STILE][STILE];
    __shared__ double s_warp[32];

    const int tx = threadIdx.x;            // 0..31 (w within tile)
    const int ty = threadIdx.y;            // 0..31 (h within tile)
    const int tid = ty * TILE + tx;        // 0..1023
    const int b  = blockIdx.z;
    const int h0 = blockIdx.y * TILE;
    const int w0 = blockIdx.x * TILE;
    const int planeOff = b * (H_DIM * W_DIM);

    // ---- Load 48x48 seed tile (with halo, clamped -> no seed) ----
    #pragma unroll
    for (int c = tid; c < STILE * STILE; c += 1024) {
        int cy = c / STILE;
        int cx = c - cy * STILE;
        int gh = h0 - HALO + cy;
        int gw = w0 - HALO + cx;
        unsigned char v = 0;
        if (gh >= 0 && gh < H_DIM && gw >= 0 && gw < W_DIM) {
            v = (targets[planeOff + gh * W_DIM + gw] > 0) ? 1 : 0;
        }
        s_seed[cy][cx] = v;
    }
    __syncthreads();

    const int ly = ty + HALO;
    const int lx = tx + HALO;
    const int gh = h0 + ty;
    const int gw = w0 + tx;

    // ---- Exact nearest-seed squared distance via expanding Chebyshev rings ----
    int best = 0x3fffffff;
    if (s_seed[ly][lx]) {
        best = 0;
    } else {
        #pragma unroll 1
        for (int r = 1; r <= HALO; ++r) {
            if (r * r >= best) break;
            const int rr = r * r;
            const int yT = ly - r, yB = ly + r;
            // top & bottom rows of the ring
            for (int dx = -r; dx <= r; ++dx) {
                int d2 = rr + dx * dx;
                if (d2 < best) {
                    int x = lx + dx;
                    if (s_seed[yT][x]) best = d2;
                    if (s_seed[yB][x] && d2 < best) best = d2;
                }
            }
            // left & right columns (excluding corners)
            const int xL = lx - r, xR = lx + r;
            for (int dy = -r + 1; dy <= r - 1; ++dy) {
                int d2 = rr + dy * dy;
                if (d2 < best) {
                    int y = ly + dy;
                    if (s_seed[y][xL]) best = d2;
                    if (s_seed[y][xR] && d2 < best) best = d2;
                }
            }
        }
        // ---- Rare exact fallback: search beyond halo in global memory ----
        if ((HALO + 1) * (HALO + 1) < best) {
            for (int r = HALO + 1; r < H_DIM + W_DIM; ++r) {
                if (r * r >= best) break;
                const int rr = r * r;
                const int yT = gh - r, yB = gh + r;
                for (int dx = -r; dx <= r; ++dx) {
                    int d2 = rr + dx * dx;
                    if (d2 >= best) continue;
                    int x = gw + dx;
                    if (x < 0 || x >= W_DIM) continue;
                    if (yT >= 0 && targets[planeOff + yT * W_DIM + x] > 0) best = d2;
                    if (yB < H_DIM && d2 < best && targets[planeOff + yB * W_DIM + x] > 0) best = d2;
                }
                const int xL = gw - r, xR = gw + r;
                for (int dy = -r + 1; dy <= r - 1; ++dy) {
                    int d2 = rr + dy * dy;
                    if (d2 >= best) continue;
                    int y = gh + dy;
                    if (y < 0 || y >= H_DIM) continue;
                    if (xL >= 0 && targets[planeOff + y * W_DIM + xL] > 0) best = d2;
                    if (xR < W_DIM && d2 < best && targets[planeOff + y * W_DIM + xR] > 0) best = d2;
                }
            }
        }
    }

    float dist = (best == 0) ? 0.0f : sqrtf((float)best);

    // ---- Fused loss contribution: p*dist + (1 - p), p = sigmoid(logit) ----
    float x = logits[planeOff + gh * W_DIM + gw];
    float p = 1.0f / (1.0f + __expf(-x));
    double contrib = (double)(p * dist) + (double)(1.0f - p);

    // ---- Block reduction (deterministic, double precision) ----
    #pragma unroll
    for (int off = 16; off > 0; off >>= 1)
        contrib += __shfl_down_sync(0xffffffffu, contrib, off);

    const int lane = tid & 31;
    const int warp = tid >> 5;
    if (lane == 0) s_warp[warp] = contrib;
    __syncthreads();
    if (warp == 0) {
        double v = s_warp[lane];  // 32 warps exactly
        #pragma unroll
        for (int off = 16; off > 0; off >>= 1)
            v += __shfl_down_sync(0xffffffffu, v, off);
        if (lane == 0) {
            int blockIndex = (blockIdx.z * NBLK_Y + blockIdx.y) * NBLK_X + blockIdx.x;
            g_blockSums[blockIndex] = v;
        }
    }
}

// ---------------------------------------------------------------------------
// Kernel 2: final reduction of 400 block sums -> scalar mean
// ---------------------------------------------------------------------------
__global__ void final_reduce_kernel(float* __restrict__ out, int n_total)
{
    __shared__ double s_warp[16];
    const int tid = threadIdx.x;  // 512 threads
    double v = 0.0;
    for (int i = tid; i < NBLOCKS; i += 512) v += g_blockSums[i];
    #pragma unroll
    for (int off = 16; off > 0; off >>= 1)
        v += __shfl_down_sync(0xffffffffu, v, off);
    const int lane = tid & 31;
    const int warp = tid >> 5;
    if (lane == 0) s_warp[warp] = v;
    __syncthreads();
    if (warp == 0) {
        double t = (lane < 16) ? s_warp[lane] : 0.0;
        #pragma unroll
        for (int off = 8; off > 0; off >>= 1)
            t += __shfl_down_sync(0xffffffffu, t, off);
        if (lane == 0) out[0] = (float)(t / (double)n_total);
    }
}

extern "C" void kernel_launch(void* const* d_in, const int* in_sizes, int n_in,
                              void* d_out, int out_size)
{
    const float* logits  = (const float*)d_in[0];
    const int*   targets = (const int*)d_in[1];
    float* out = (float*)d_out;
    const int n_total = in_sizes[0];  // B*H*W = 409600

    dim3 block(TILE, TILE, 1);
    dim3 grid(NBLK_X, NBLK_Y, B_DIM);
    edt_loss_kernel<<<grid, block>>>(logits, targets);
    final_reduce_kernel<<<1, 512>>>(out, n_total);
}

// round 2
// speedup vs baseline: 1.2262x; 1.2262x over previous
#include <cuda_runtime.h>
#include <cuda_bf16.h>
#include <math.h>

// Problem constants (fixed by dataset: B=4, H=W=320)
#define H_DIM 320
#define W_DIM 320
#define B_DIM 4
#define TILE 32                 // tile is 32x32 pixels
#define BLK_Y 16                // 32x16 threads, 2 pixels per thread
#define HALO 8
#define SROWS (TILE + 2 * HALO) // 48 mask rows
#define NBLK_X (W_DIM / TILE)   // 10
#define NBLK_Y (H_DIM / TILE)   // 10
#define NBLOCKS (NBLK_X * NBLK_Y * B_DIM) // 400

__device__ double g_blockSums[NBLOCKS];
__device__ unsigned int g_arrived = 0;

// Nearest-seed squared distance for center (ry, tx) in mask coordinates.
// Mask row m: bit c corresponds to global col (w0 - 8 + c), c in [0,48).
// Window of 17 bits centered at bit (tx + 8) => dx in [-8, 8].
__device__ __forceinline__ int nearest_d2(const unsigned long long* s_mask,
                                          int ry, int tx)
{
    int best = 0x7fffffff;

    // dy = 0
    {
        unsigned int w = (unsigned int)(s_mask[ry] >> tx) & 0x1FFFFu;
        if (w) {
            unsigned int r = w >> 8;          // dx = 0..8
            unsigned int l = w & 0x1FFu;      // dx = -8..0 (bit b -> dx = b-8)
            int dxr = r ? (__ffs(r) - 1) : 1000;
            int dxl = l ? (__clz(l) - 23) : 1000;   // 8 - (31 - clz) = clz - 23
            int dx = min(dxr, dxl);
            best = dx * dx;
        }
    }
    #pragma unroll 1
    for (int d = 1; d <= HALO; ++d) {
        int dy2 = d * d;
        if (dy2 >= best) break;
        #pragma unroll
        for (int s = 0; s < 2; ++s) {
            int row = s ? (ry + d) : (ry - d);
            unsigned int w = (unsigned int)(s_mask[row] >> tx) & 0x1FFFFu;
            if (w) {
                unsigned int r = w >> 8;
                unsigned int l = w & 0x1FFu;
                int dxr = r ? (__ffs(r) - 1) : 1000;
                int dxl = l ? (__clz(l) - 23) : 1000;
                int dx = min(dxr, dxl);
                int cand = dy2 + dx * dx;
                best = min(best, cand);
            }
        }
    }
    return best;
}

// Exact global fallback for the (essentially impossible with dense random
// seeds, but required for exactness) case where no seed lies within the
// Chebyshev-8 window: any point outside that window has d^2 >= 81.
__device__ int global_ring_search(const int* __restrict__ targets,
                                  int planeOff, int gh, int gw, int best)
{
    for (int r = HALO + 1; r < H_DIM + W_DIM; ++r) {
        if (r * r >= best) break;
        const int rr = r * r;
        const int yT = gh - r, yB = gh + r;
        for (int dx = -r; dx <= r; ++dx) {
            int d2 = rr + dx * dx;
            if (d2 >= best) continue;
            int x = gw + dx;
            if (x < 0 || x >= W_DIM) continue;
            if (yT >= 0 && targets[planeOff + yT * W_DIM + x] > 0) best = d2;
            if (yB < H_DIM && d2 < best && targets[planeOff + yB * W_DIM + x] > 0) best = d2;
        }
        const int xL = gw - r, xR = gw + r;
        for (int dy = -r + 1; dy <= r - 1; ++dy) {
            int d2 = rr + dy * dy;
            if (d2 >= best) continue;
            int y = gh + dy;
            if (y < 0 || y >= H_DIM) continue;
            if (xL >= 0 && targets[planeOff + y * W_DIM + xL] > 0) best = d2;
            if (xR < W_DIM && d2 < best && targets[planeOff + y * W_DIM + xR] > 0) best = d2;
        }
    }
    return best;
}

__global__ __launch_bounds__(512)
void edt_loss_kernel(const float* __restrict__ logits,
                     const int* __restrict__ targets,
                     float* __restrict__ out)
{
    __shared__ unsigned long long s_mask[SROWS];
    __shared__ double s_warp[16];
    __shared__ int s_isLast;

    const int tx   = threadIdx.x;                 // 0..31
    const int ty   = threadIdx.y;                 // 0..15
    const int tid  = ty * 32 + tx;                // 0..511
    const int warp = tid >> 5;                    // == ty
    const int lane = tid & 31;                    // == tx
    const int b  = blockIdx.z;
    const int h0 = blockIdx.y * TILE;
    const int w0 = blockIdx.x * TILE;
    const int planeOff = b * (H_DIM * W_DIM);

    // ---- Build 48 row bitmasks (48 bits each) via warp ballots ----
    // Warp w handles mask rows w, w+16, w+32.
    #pragma unroll
    for (int k = 0; k < 3; ++k) {
        int hr = warp + k * 16;                   // 0..47
        int grow = h0 - HALO + hr;
        unsigned long long m = 0ull;
        if (grow >= 0 && grow < H_DIM) {
            const int* rowp = targets + planeOff + grow * W_DIM;
            // bits 0..31
            int c0 = w0 - HALO + lane;
            bool p0 = (c0 >= 0 && c0 < W_DIM) && (rowp[c0] > 0);
            unsigned int lo = __ballot_sync(0xffffffffu, p0);
            // bits 32..47 (lanes 0..15)
            int c1 = w0 + 24 + lane;
            bool p1 = (lane < 16) && (c1 < W_DIM) && (rowp[c1] > 0);
            unsigned int hi = __ballot_sync(0xffffffffu, p1);
            m = (unsigned long long)lo | ((unsigned long long)(hi & 0xFFFFu) << 32);
        }
        s_mask[hr] = m;
    }
    __syncthreads();

    // ---- Two pixels per thread: (ty, tx) and (ty+16, tx) within tile ----
    double acc = 0.0;
    #pragma unroll
    for (int half = 0; half < 2; ++half) {
        const int py = ty + half * 16;            // 0..31
        const int ry = py + HALO;                 // mask row of center
        const int gh = h0 + py;
        const int gw = w0 + tx;

        int best = nearest_d2(s_mask, ry, tx);
        if (best > 81) {  // possible nearer seed outside the 17x17 window
            best = global_ring_search(targets, planeOff, gh, gw, best);
        }
        float dist = sqrtf((float)best);

        float x = logits[planeOff + gh * W_DIM + gw];
        float p = 1.0f / (1.0f + __expf(-x));
        acc += (double)(p * dist) + (double)(1.0f - p);
    }

    // ---- Deterministic block reduction (double) ----
    #pragma unroll
    for (int off = 16; off > 0; off >>= 1)
        acc += __shfl_down_sync(0xffffffffu, acc, off);
    if (lane == 0) s_warp[warp] = acc;
    __syncthreads();
    if (warp == 0) {
        double v = (lane < 16) ? s_warp[lane] : 0.0;
        #pragma unroll
        for (int off = 8; off > 0; off >>= 1)
            v += __shfl_down_sync(0xffffffffu, v, off);
        if (lane == 0) {
            int blockIndex = (blockIdx.z * NBLK_Y + blockIdx.y) * NBLK_X + blockIdx.x;
            g_blockSums[blockIndex] = v;
        }
    }

    // ---- Last-arriving block performs the final reduction ----
    if (tid == 0) {
        __threadfence();
        unsigned int t = atomicAdd(&g_arrived, 1u);
        s_isLast = (t == (unsigned int)(NBLOCKS - 1)) ? 1 : 0;
    }
    __syncthreads();
    if (s_isLast) {
        double v = 0.0;
        for (int i = tid; i < NBLOCKS; i += 512) v += g_blockSums[i];
        #pragma unroll
        for (int off = 16; off > 0; off >>= 1)
            v += __shfl_down_sync(0xffffffffu, v, off);
        if (lane == 0) s_warp[warp] = v;
        __syncthreads();
        if (warp == 0) {
            double t = (lane < 16) ? s_warp[lane] : 0.0;
            #pragma unroll
            for (int off = 8; off > 0; off >>= 1)
                t += __shfl_down_sync(0xffffffffu, t, off);
            if (lane == 0) {
                out[0] = (float)(t / (double)(B_DIM * H_DIM * W_DIM));
                g_arrived = 0;   // reset for next graph replay
            }
        }
    }
}

extern "C" void kernel_launch(void* const* d_in, const int* in_sizes, int n_in,
                              void* d_out, int out_size)
{
    const float* logits  = (const float*)d_in[0];
    const int*   targets = (const int*)d_in[1];
    float* out = (float*)d_out;

    dim3 block(32, BLK_Y, 1);
    dim3 grid(NBLK_X, NBLK_Y, B_DIM);
    edt_loss_kernel<<<grid, block>>>(logits, targets, out);
}

// round 3
// speedup vs baseline: 1.2424x; 1.0133x over previous
#include <cuda_runtime.h>
#include <cuda_bf16.h>
#include <math.h>

// Problem constants (fixed by dataset: B=4, H=W=320)
#define H_DIM 320
#define W_DIM 320
#define B_DIM 4
#define TILE 32                 // tile is 32x32 pixels
#define BLK_Y 16                // 32x16 threads, 2 pixels per thread
#define HALO 8
#define SROWS (TILE + 2 * HALO) // 48 mask rows
#define NBLK_X (W_DIM / TILE)   // 10
#define NBLK_Y (H_DIM / TILE)   // 10
#define NBLOCKS (NBLK_X * NBLK_Y * B_DIM) // 400

__device__ double g_blockSums[NBLOCKS];
__device__ unsigned int g_arrived = 0;

// Exact global fallback for the (essentially impossible with dense random
// seeds, but required for exactness) case where no seed within Chebyshev-8
// beats what's outside: any point outside that window has d^2 >= 81.
__device__ __noinline__ int global_ring_search(const int* __restrict__ targets,
                                               int planeOff, int gh, int gw, int best)
{
    for (int r = HALO + 1; r < H_DIM + W_DIM; ++r) {
        if (r * r >= best) break;
        const int rr = r * r;
        const int yT = gh - r, yB = gh + r;
        for (int dx = -r; dx <= r; ++dx) {
            int d2 = rr + dx * dx;
            if (d2 >= best) continue;
            int x = gw + dx;
            if (x < 0 || x >= W_DIM) continue;
            if (yT >= 0 && targets[planeOff + yT * W_DIM + x] > 0) best = d2;
            if (yB < H_DIM && d2 < best && targets[planeOff + yB * W_DIM + x] > 0) best = d2;
        }
        const int xL = gw - r, xR = gw + r;
        for (int dy = -r + 1; dy <= r - 1; ++dy) {
            int d2 = rr + dy * dy;
            if (d2 >= best) continue;
            int y = gh + dy;
            if (y < 0 || y >= H_DIM) continue;
            if (xL >= 0 && targets[planeOff + y * W_DIM + xL] > 0) best = d2;
            if (xR < W_DIM && d2 < best && targets[planeOff + y * W_DIM + xR] > 0) best = d2;
        }
    }
    return best;
}

// Branchless nearest-seed d^2 within the 17x17 window centered at (ry, tx+8).
// All 17 LDS are independent broadcasts (whole warp reads same row) -> MLP.
__device__ __forceinline__ int window_d2(const unsigned long long* __restrict__ s_mask,
                                         int ry, int tx)
{
    unsigned int win[17];
    #pragma unroll
    for (int i = 0; i < 17; ++i)
        win[i] = (unsigned int)(s_mask[ry - 8 + i] >> tx) & 0x1FFFFu;

    int best;
    {   // d = 0
        unsigned int u = win[8];
        unsigned int r = u >> 8;
        unsigned int l = u & 0x1FFu;
        int dxr = r ? (__ffs(r) - 1) : 1000;
        int dxl = l ? (__clz(l) - 23) : 1000;
        int dx = min(dxr, dxl);
        best = min(dx * dx, 0x0fffffff);
    }
    #pragma unroll
    for (int d = 1; d <= 8; ++d) {
        unsigned int u = win[8 - d] | win[8 + d];
        unsigned int r = u >> 8;
        unsigned int l = u & 0x1FFu;
        int dxr = r ? (__ffs(r) - 1) : 1000;
        int dxl = l ? (__clz(l) - 23) : 1000;
        int dx = min(dxr, dxl);
        int cand = d * d + dx * dx;
        best = min(best, cand);
    }
    return best;
}

__global__ __launch_bounds__(512)
void edt_loss_kernel(const float* __restrict__ logits,
                     const int* __restrict__ targets,
                     float* __restrict__ out)
{
    __shared__ unsigned long long s_mask[SROWS];
    __shared__ double s_warp[16];
    __shared__ int s_isLast;

    const int tx   = threadIdx.x;                 // 0..31
    const int ty   = threadIdx.y;                 // 0..15
    const int tid  = ty * 32 + tx;                // 0..511
    const int warp = tid >> 5;                    // == ty
    const int lane = tid & 31;                    // == tx
    const int h0 = blockIdx.y * TILE;
    const int w0 = blockIdx.x * TILE;
    const int planeOff = blockIdx.z * (H_DIM * W_DIM);

    // ---- Hoist logit loads (overlap global latency with mask build/search) ----
    const int gw = w0 + tx;
    float x0 = logits[planeOff + (h0 + ty) * W_DIM + gw];
    float x1 = logits[planeOff + (h0 + ty + 16) * W_DIM + gw];

    // ---- Build 48 row bitmasks (48 bits each) via warp ballots ----
    // Warp w handles mask rows w, w+16, w+32.
    #pragma unroll
    for (int k = 0; k < 3; ++k) {
        int hr = warp + k * 16;                   // 0..47
        int grow = h0 - HALO + hr;
        unsigned long long m = 0ull;
        if (grow >= 0 && grow < H_DIM) {
            const int* rowp = targets + planeOff + grow * W_DIM;
            int c0 = w0 - HALO + lane;
            bool p0 = (c0 >= 0 && c0 < W_DIM) && (rowp[c0] > 0);
            unsigned int lo = __ballot_sync(0xffffffffu, p0);
            int c1 = w0 + 24 + lane;
            bool p1 = (lane < 16) && (c1 < W_DIM) && (rowp[c1] > 0);
            unsigned int hi = __ballot_sync(0xffffffffu, p1);
            m = (unsigned long long)lo | ((unsigned long long)(hi & 0xFFFFu) << 32);
        }
        s_mask[hr] = m;
    }
    __syncthreads();

    // ---- Two pixels per thread: (ty, tx) and (ty+16, tx) within tile ----
    double acc = 0.0;
    {
        int best = window_d2(s_mask, ty + HALO, tx);
        if (best > 81)
            best = global_ring_search(targets, planeOff, h0 + ty, gw, best);
        float dist = sqrtf((float)best);
        float p = 1.0f / (1.0f + __expf(-x0));
        acc += (double)(p * dist) + (double)(1.0f - p);
    }
    {
        int best = window_d2(s_mask, ty + 16 + HALO, tx);
        if (best > 81)
            best = global_ring_search(targets, planeOff, h0 + ty + 16, gw, best);
        float dist = sqrtf((float)best);
        float p = 1.0f / (1.0f + __expf(-x1));
        acc += (double)(p * dist) + (double)(1.0f - p);
    }

    // ---- Deterministic block reduction (double) ----
    #pragma unroll
    for (int off = 16; off > 0; off >>= 1)
        acc += __shfl_down_sync(0xffffffffu, acc, off);
    if (lane == 0) s_warp[warp] = acc;
    __syncthreads();
    if (warp == 0) {
        double v = (lane < 16) ? s_warp[lane] : 0.0;
        #pragma unroll
        for (int off = 8; off > 0; off >>= 1)
            v += __shfl_down_sync(0xffffffffu, v, off);
        if (lane == 0) {
            int blockIndex = (blockIdx.z * NBLK_Y + blockIdx.y) * NBLK_X + blockIdx.x;
            g_blockSums[blockIndex] = v;
        }
    }

    // ---- Last-arriving block performs the final reduction ----
    if (tid == 0) {
        __threadfence();
        unsigned int t = atomicAdd(&g_arrived, 1u);
        s_isLast = (t == (unsigned int)(NBLOCKS - 1)) ? 1 : 0;
    }
    __syncthreads();
    if (s_isLast) {
        double v = 0.0;
        for (int i = tid; i < NBLOCKS; i += 512) v += g_blockSums[i];
        #pragma unroll
        for (int off = 16; off > 0; off >>= 1)
            v += __shfl_down_sync(0xffffffffu, v, off);
        if (lane == 0) s_warp[warp] = v;
        __syncthreads();
        if (warp == 0) {
            double t = (lane < 16) ? s_warp[lane] : 0.0;
            #pragma unroll
            for (int off = 8; off > 0; off >>= 1)
                t += __shfl_down_sync(0xffffffffu, t, off);
            if (lane == 0) {
                out[0] = (float)(t / (double)(B_DIM * H_DIM * W_DIM));
                g_arrived = 0;   // reset for next graph replay
            }
        }
    }
}

extern "C" void kernel_launch(void* const* d_in, const int* in_sizes, int n_in,
                              void* d_out, int out_size)
{
    const float* logits  = (const float*)d_in[0];
    const int*   targets = (const int*)d_in[1];
    float* out = (float*)d_out;

    dim3 block(32, BLK_Y, 1);
    dim3 grid(NBLK_X, NBLK_Y, B_DIM);
    edt_loss_kernel<<<grid, block>>>(logits, targets, out);
}

// round 4
// speedup vs baseline: 1.3898x; 1.1186x over previous
#include <cuda_runtime.h>
#include <cuda_bf16.h>
#include <math.h>

// Problem constants (fixed by dataset: B=4, H=W=320)
#define H_DIM 320
#define W_DIM 320
#define B_DIM 4
#define TILE 32                 // tile is 32x32 pixels
#define BLK_Y 16                // 32x16 threads, 2 pixels per thread
#define HALO 8
#define SROWS (TILE + 2 * HALO) // 48 rows incl. halo
#define NBLK_X (W_DIM / TILE)   // 10
#define NBLK_Y (H_DIM / TILE)   // 10
#define NBLOCKS (NBLK_X * NBLK_Y * B_DIM) // 400

__device__ double g_blockSums[NBLOCKS];
__device__ unsigned int g_arrived = 0;

// Exact global fallback (required for exactness when no seed within the
// Chebyshev-8 window beats the outside: outside => d^2 >= 81).
__device__ __noinline__ int global_ring_search(const int* __restrict__ targets,
                                               int planeOff, int gh, int gw, int best)
{
    for (int r = HALO + 1; r < H_DIM + W_DIM; ++r) {
        if (r * r >= best) break;
        const int rr = r * r;
        const int yT = gh - r, yB = gh + r;
        for (int dx = -r; dx <= r; ++dx) {
            int d2 = rr + dx * dx;
            if (d2 >= best) continue;
            int x = gw + dx;
            if (x < 0 || x >= W_DIM) continue;
            if (yT >= 0 && targets[planeOff + yT * W_DIM + x] > 0) best = d2;
            if (yB < H_DIM && d2 < best && targets[planeOff + yB * W_DIM + x] > 0) best = d2;
        }
        const int xL = gw - r, xR = gw + r;
        for (int dy = -r + 1; dy <= r - 1; ++dy) {
            int d2 = rr + dy * dy;
            if (d2 >= best) continue;
            int y = gh + dy;
            if (y < 0 || y >= H_DIM) continue;
            if (xL >= 0 && targets[planeOff + y * W_DIM + xL] > 0) best = d2;
            if (xR < W_DIM && d2 < best && targets[planeOff + y * W_DIM + xR] > 0) best = d2;
        }
    }
    return best;
}

// Vertical min-plus over the precomputed per-row horizontal distances.
// col points at s_dxsq[0][tx]; rows are stride-32 bytes apart.
__device__ __forceinline__ int vertical_min(const unsigned char* __restrict__ col, int ry)
{
    const unsigned char* c = col + ry * 32;
    int b0 = (int)c[0];                                        // d = 0
    int b1 = min((int)c[-1 * 32], (int)c[ 1 * 32]) + 1;        // d = 1
    int b2 = min((int)c[-2 * 32], (int)c[ 2 * 32]) + 4;
    int b3 = min((int)c[-3 * 32], (int)c[ 3 * 32]) + 9;
    int b4 = min((int)c[-4 * 32], (int)c[ 4 * 32]) + 16;
    int b5 = min((int)c[-5 * 32], (int)c[ 5 * 32]) + 25;
    int b6 = min((int)c[-6 * 32], (int)c[ 6 * 32]) + 36;
    int b7 = min((int)c[-7 * 32], (int)c[ 7 * 32]) + 49;
    int b8 = min((int)c[-8 * 32], (int)c[ 8 * 32]) + 64;
    int m01 = min(b0, b1), m23 = min(b2, b3);
    int m45 = min(b4, b5), m67 = min(b6, b7);
    int m03 = min(m01, m23), m47 = min(m45, m67);
    return min(min(m03, m47), b8);
}

__global__ __launch_bounds__(512)
void edt_loss_kernel(const float* __restrict__ logits,
                     const int* __restrict__ targets,
                     float* __restrict__ out)
{
    __shared__ unsigned char s_dxsq[SROWS][32];   // per (row, col): nearest dx^2 (<=64) or 127
    __shared__ double s_warp[16];
    __shared__ int s_isLast;

    const int tx   = threadIdx.x;                 // 0..31 (== lane)
    const int ty   = threadIdx.y;                 // 0..15 (== warp)
    const int tid  = ty * 32 + tx;
    const int warp = ty;
    const int lane = tx;
    const int h0 = blockIdx.y * TILE;
    const int w0 = blockIdx.x * TILE;
    const int planeOff = blockIdx.z * (H_DIM * W_DIM);
    const int gw = w0 + tx;

    // ---- Hoist logit loads (overlap global latency with EDT work) ----
    float x0 = logits[planeOff + (h0 + ty) * W_DIM + gw];
    float x1 = logits[planeOff + (h0 + ty + 16) * W_DIM + gw];

    // ---- Fused: ballot-build mask row (kept in register) + horizontal pass ----
    // Warp w handles rows w, w+16, w+32. Bit c of mask = seed at col (w0-8+c).
    #pragma unroll
    for (int k = 0; k < 3; ++k) {
        int hr = warp + k * 16;                   // 0..47
        int grow = h0 - HALO + hr;
        unsigned long long m = 0ull;
        if (grow >= 0 && grow < H_DIM) {
            const int* rowp = targets + planeOff + grow * W_DIM;
            int c0 = w0 - HALO + lane;
            bool p0 = (c0 >= 0 && c0 < W_DIM) && (rowp[c0] > 0);
            unsigned int lo = __ballot_sync(0xffffffffu, p0);
            int c1 = w0 + 24 + lane;
            bool p1 = (lane < 16) && (c1 < W_DIM) && (rowp[c1] > 0);
            unsigned int hi = __ballot_sync(0xffffffffu, p1);
            m = (unsigned long long)lo | ((unsigned long long)(hi & 0xFFFFu) << 32);
        }
        // nearest |dx| in this row within +/-8 of column tx
        unsigned int win = (unsigned int)(m >> tx) & 0x1FFFFu;
        unsigned int r = win >> 8;                 // dx = 0..8
        unsigned int l = win & 0x1FFu;             // dx = -8..0
        int dxr = r ? (__ffs(r) - 1) : 127;
        int dxl = l ? (__clz(l) - 23) : 127;
        int dx = min(dxr, dxl);
        s_dxsq[hr][tx] = (unsigned char)min(dx * dx, 127);
    }
    __syncthreads();

    // ---- Two pixels per thread: vertical min-plus + fused loss ----
    const unsigned char* col = &s_dxsq[0][tx];
    double acc = 0.0;
    {
        int best = vertical_min(col, ty + HALO);
        if (best > 81)
            best = global_ring_search(targets, planeOff, h0 + ty, gw, best);
        float dist = sqrtf((float)best);
        float p = 1.0f / (1.0f + __expf(-x0));
        acc += (double)(p * dist) + (double)(1.0f - p);
    }
    {
        int best = vertical_min(col, ty + 16 + HALO);
        if (best > 81)
            best = global_ring_search(targets, planeOff, h0 + ty + 16, gw, best);
        float dist = sqrtf((float)best);
        float p = 1.0f / (1.0f + __expf(-x1));
        acc += (double)(p * dist) + (double)(1.0f - p);
    }

    // ---- Deterministic block reduction (double) ----
    #pragma unroll
    for (int off = 16; off > 0; off >>= 1)
        acc += __shfl_down_sync(0xffffffffu, acc, off);
    if (lane == 0) s_warp[warp] = acc;
    __syncthreads();
    if (warp == 0) {
        double v = (lane < 16) ? s_warp[lane] : 0.0;
        #pragma unroll
        for (int off = 8; off > 0; off >>= 1)
            v += __shfl_down_sync(0xffffffffu, v, off);
        if (lane == 0) {
            int blockIndex = (blockIdx.z * NBLK_Y + blockIdx.y) * NBLK_X + blockIdx.x;
            g_blockSums[blockIndex] = v;
        }
    }

    // ---- Last-arriving block performs the final reduction ----
    if (tid == 0) {
        __threadfence();
        unsigned int t = atomicAdd(&g_arrived, 1u);
        s_isLast = (t == (unsigned int)(NBLOCKS - 1)) ? 1 : 0;
    }
    __syncthreads();
    if (s_isLast) {
        double v = 0.0;
        for (int i = tid; i < NBLOCKS; i += 512) v += g_blockSums[i];
        #pragma unroll
        for (int off = 16; off > 0; off >>= 1)
            v += __shfl_down_sync(0xffffffffu, v, off);
        if (lane == 0) s_warp[warp] = v;
        __syncthreads();
        if (warp == 0) {
            double t = (lane < 16) ? s_warp[lane] : 0.0;
            #pragma unroll
            for (int off = 8; off > 0; off >>= 1)
                t += __shfl_down_sync(0xffffffffu, t, off);
            if (lane == 0) {
                out[0] = (float)(t / (double)(B_DIM * H_DIM * W_DIM));
                g_arrived = 0;   // reset for next graph replay
            }
        }
    }
}

extern "C" void kernel_launch(void* const* d_in, const int* in_sizes, int n_in,
                              void* d_out, int out_size)
{
    const float* logits  = (const float*)d_in[0];
    const int*   targets = (const int*)d_in[1];
    float* out = (float*)d_out;

    dim3 block(32, BLK_Y, 1);
    dim3 grid(NBLK_X, NBLK_Y, B_DIM);
    edt_loss_kernel<<<grid, block>>>(logits, targets, out);
}

// round 5
// speedup vs baseline: 2.4207x; 1.7417x over previous
#include <cuda_runtime.h>
#include <cuda_bf16.h>
#include <math.h>

// Problem constants (fixed by dataset: B=4, H=W=320)
#define H_DIM 320
#define W_DIM 320
#define B_DIM 4
#define TILE 32                 // tile is 32x32 pixels
#define BLK_Y 16                // 32x16 threads, 2 pixels per thread
#define HALO 8
#define SROWS (TILE + 2 * HALO) // 48 rows incl. halo
#define NBLK_X (W_DIM / TILE)   // 10
#define NBLK_Y (H_DIM / TILE)   // 10
#define NBLOCKS (NBLK_X * NBLK_Y * B_DIM) // 400

__device__ float g_blockSums[NBLOCKS];
__device__ unsigned int g_arrived = 0;

// Exact global fallback (required for exactness when no seed within the
// Chebyshev-8 window beats the outside: outside => d^2 >= 81).
__device__ __noinline__ int global_ring_search(const int* __restrict__ targets,
                                               int planeOff, int gh, int gw, int best)
{
    for (int r = HALO + 1; r < H_DIM + W_DIM; ++r) {
        if (r * r >= best) break;
        const int rr = r * r;
        const int yT = gh - r, yB = gh + r;
        for (int dx = -r; dx <= r; ++dx) {
            int d2 = rr + dx * dx;
            if (d2 >= best) continue;
            int x = gw + dx;
            if (x < 0 || x >= W_DIM) continue;
            if (yT >= 0 && targets[planeOff + yT * W_DIM + x] > 0) best = d2;
            if (yB < H_DIM && d2 < best && targets[planeOff + yB * W_DIM + x] > 0) best = d2;
        }
        const int xL = gw - r, xR = gw + r;
        for (int dy = -r + 1; dy <= r - 1; ++dy) {
            int d2 = rr + dy * dy;
            if (d2 >= best) continue;
            int y = gh + dy;
            if (y < 0 || y >= H_DIM) continue;
            if (xL >= 0 && targets[planeOff + y * W_DIM + xL] > 0) best = d2;
            if (xR < W_DIM && d2 < best && targets[planeOff + y * W_DIM + xR] > 0) best = d2;
        }
    }
    return best;
}

// Vertical min-plus over per-row horizontal distances (uint32, conflict-free).
// col points at s_dxsq[0][tx]; rows are 32 words apart.
__device__ __forceinline__ int vertical_min(const unsigned int* __restrict__ col, int ry)
{
    const unsigned int* c = col + ry * 32;
    int b0 = (int)c[0];
    int b1 = min((int)c[-1 * 32], (int)c[ 1 * 32]) + 1;
    int b2 = min((int)c[-2 * 32], (int)c[ 2 * 32]) + 4;
    int b3 = min((int)c[-3 * 32], (int)c[ 3 * 32]) + 9;
    int b4 = min((int)c[-4 * 32], (int)c[ 4 * 32]) + 16;
    int b5 = min((int)c[-5 * 32], (int)c[ 5 * 32]) + 25;
    int b6 = min((int)c[-6 * 32], (int)c[ 6 * 32]) + 36;
    int b7 = min((int)c[-7 * 32], (int)c[ 7 * 32]) + 49;
    int b8 = min((int)c[-8 * 32], (int)c[ 8 * 32]) + 64;
    int m01 = min(b0, b1), m23 = min(b2, b3);
    int m45 = min(b4, b5), m67 = min(b6, b7);
    int m03 = min(m01, m23), m47 = min(m45, m67);
    return min(min(m03, m47), b8);
}

__global__ __launch_bounds__(512)
void edt_loss_kernel(const float* __restrict__ logits,
                     const int* __restrict__ targets,
                     float* __restrict__ out)
{
    __shared__ unsigned int s_dxsq[SROWS][32];    // nearest dx^2 per (row, col); 6 KB
    __shared__ float s_warp[16];
    __shared__ int s_isLast;

    const int tx   = threadIdx.x;                 // 0..31 (== lane)
    const int ty   = threadIdx.y;                 // 0..15 (== warp)
    const int tid  = ty * 32 + tx;
    const int warp = ty;
    const int lane = tx;
    const int h0 = blockIdx.y * TILE;
    const int w0 = blockIdx.x * TILE;
    const int planeOff = blockIdx.z * (H_DIM * W_DIM);
    const int gw = w0 + tx;

    // ---- Hoist ALL global loads: one memory round, MLP = 8 ----
    float x0 = logits[planeOff + (h0 + ty) * W_DIM + gw];
    float x1 = logits[planeOff + (h0 + ty + 16) * W_DIM + gw];

    const int* rowBase = targets + planeOff;
    int av[3] = {0, 0, 0};
    int bv[3] = {0, 0, 0};
    #pragma unroll
    for (int k = 0; k < 3; ++k) {
        int grow = h0 - HALO + warp + k * 16;     // 0..47 -> global row
        bool rv = (grow >= 0) && (grow < H_DIM);
        int c0 = w0 - HALO + lane;
        if (rv && c0 >= 0 && c0 < W_DIM) av[k] = __ldg(rowBase + grow * W_DIM + c0);
        int c1 = w0 + 24 + lane;
        if (rv && lane < 16 && c1 < W_DIM)  bv[k] = __ldg(rowBase + grow * W_DIM + c1);
    }

    // ---- Ballot-assemble 48-bit row masks + horizontal nearest-dx pass ----
    #pragma unroll
    for (int k = 0; k < 3; ++k) {
        unsigned int lo = __ballot_sync(0xffffffffu, av[k] > 0);
        unsigned int hi = __ballot_sync(0xffffffffu, bv[k] > 0); // lanes>=16 give 0
        unsigned long long m =
            (unsigned long long)lo | ((unsigned long long)(hi & 0xFFFFu) << 32);
        unsigned int win = (unsigned int)(m >> tx) & 0x1FFFFu;
        unsigned int r = win >> 8;                 // dx = 0..8
        unsigned int l = win & 0x1FFu;             // dx = -8..0
        int dxr = r ? (__ffs(r) - 1) : 127;
        int dxl = l ? (__clz(l) - 23) : 127;
        int dx = min(dxr, dxl);
        s_dxsq[warp + k * 16][tx] = (unsigned int)min(dx * dx, 127);
    }
    __syncthreads();

    // ---- Two pixels per thread: vertical min-plus + fused loss (FP32) ----
    const unsigned int* col = &s_dxsq[0][tx];
    float acc;
    {
        int best = vertical_min(col, ty + HALO);
        if (best > 81)
            best = global_ring_search(targets, planeOff, h0 + ty, gw, best);
        float dist = __fsqrt_rn((float)best);
        float p = 1.0f / (1.0f + __expf(-x0));
        acc = fmaf(p, dist, 1.0f - p);
    }
    {
        int best = vertical_min(col, ty + 16 + HALO);
        if (best > 81)
            best = global_ring_search(targets, planeOff, h0 + ty + 16, gw, best);
        float dist = __fsqrt_rn((float)best);
        float p = 1.0f / (1.0f + __expf(-x1));
        acc += fmaf(p, dist, 1.0f - p);
    }

    // ---- Deterministic block reduction (FP32, fixed order) ----
    #pragma unroll
    for (int off = 16; off > 0; off >>= 1)
        acc += __shfl_down_sync(0xffffffffu, acc, off);
    if (lane == 0) s_warp[warp] = acc;
    __syncthreads();
    if (warp == 0) {
        float v = (lane < 16) ? s_warp[lane] : 0.0f;
        #pragma unroll
        for (int off = 8; off > 0; off >>= 1)
            v += __shfl_down_sync(0xffffffffu, v, off);
        if (lane == 0) {
            int blockIndex = (blockIdx.z * NBLK_Y + blockIdx.y) * NBLK_X + blockIdx.x;
            g_blockSums[blockIndex] = v;
        }
    }

    // ---- Last-arriving block finishes (acq_rel atomic: no gpu-scope fence) ----
    if (tid == 0) {
        unsigned int t;
        asm volatile("atom.acq_rel.gpu.global.add.u32 %0, [%1], %2;"
                     : "=r"(t) : "l"(&g_arrived), "r"(1u) : "memory");
        s_isLast = (t == (unsigned int)(NBLOCKS - 1)) ? 1 : 0;
    }
    __syncthreads();
    if (s_isLast) {
        float v = 0.0f;
        for (int i = tid; i < NBLOCKS; i += 512) v += __ldcg(&g_blockSums[i]);
        #pragma unroll
        for (int off = 16; off > 0; off >>= 1)
            v += __shfl_down_sync(0xffffffffu, v, off);
        if (lane == 0) s_warp[warp] = v;
        __syncthreads();
        if (warp == 0) {
            float t = (lane < 16) ? s_warp[lane] : 0.0f;
            #pragma unroll
            for (int off = 8; off > 0; off >>= 1)
                t += __shfl_down_sync(0xffffffffu, t, off);
            if (lane == 0) {
                out[0] = t / (float)(B_DIM * H_DIM * W_DIM);
                g_arrived = 0;   // reset for next graph replay
            }
        }
    }
}

extern "C" void kernel_launch(void* const* d_in, const int* in_sizes, int n_in,
                              void* d_out, int out_size)
{
    const float* logits  = (const float*)d_in[0];
    const int*   targets = (const int*)d_in[1];
    float* out = (float*)d_out;

    dim3 block(32, BLK_Y, 1);
    dim3 grid(NBLK_X, NBLK_Y, B_DIM);
    edt_loss_kernel<<<grid, block>>>(logits, targets, out);
}